// round 4
// baseline (speedup 1.0000x reference)
#include <cuda_runtime.h>
#include <cstdint>
#include <math.h>

#define BATCH    256
#define SEQL     512
#define INDIM    64
#define UNITS    256
#define OUTSTEPS 64
#define OUTDIMS  32
#define G4       1024   // 4 * UNITS
#define NCTA_REC 128

typedef unsigned long long ull;

// ---------------- scratch (static device globals; no allocation) ----------------
__device__ float d_X[BATCH * SEQL * UNITS];            // conv output
__device__ float d_ZX[(size_t)SEQL * BATCH * G4];      // x@W + b, [t][b][1024]
__device__ float d_HSEQ[BATCH * SEQL * UNITS];         // encoder hidden seq
__device__ float d_FSEQ[BATCH * OUTSTEPS * UNITS];     // decoder hidden seq
__device__ float d_Hbuf[2][BATCH * UNITS];             // ping-pong h
__device__ unsigned g_cnt = 0;                          // grid barrier
__device__ unsigned g_gen = 0;

// ---------------- f32x2 helpers ----------------
__device__ __forceinline__ ull pk2(float lo, float hi) {
    ull r; asm("mov.b64 %0, {%1, %2};" : "=l"(r) : "f"(lo), "f"(hi)); return r;
}
__device__ __forceinline__ void upk2(ull v, float& lo, float& hi) {
    asm("mov.b64 {%0, %1}, %2;" : "=f"(lo), "=f"(hi) : "l"(v));
}
__device__ __forceinline__ void ffma2(ull& d, ull a, ull b) {
    asm("fma.rn.f32x2 %0, %1, %2, %0;" : "+l"(d) : "l"(a), "l"(b));
}
__device__ __forceinline__ void fadd2(ull& d, ull a) {
    asm("add.rn.f32x2 %0, %0, %1;" : "+l"(d) : "l"(a));
}

// fast, overflow-safe gate functions (MUFU-based, ~1e-6 rel err)
__device__ __forceinline__ float fast_sigmoid(float x) {
    return __fdividef(1.f, 1.f + __expf(-x));
}
__device__ __forceinline__ float fast_tanh(float x) {
    float e = __expf(-2.f * fabsf(x));
    float t = __fdividef(1.f - e, 1.f + e);
    return copysignf(t, x);
}

// ---------------- conv1d 'same' (K=5) + bias + relu, f32x2 over unit pairs ----------------
__global__ __launch_bounds__(256) void conv_relu_kernel(
    const float* __restrict__ in, const float* __restrict__ ck, const float* __restrict__ cb)
{
    __shared__ __align__(16) ull ins2[36 * 64];
    int tid = threadIdx.x;
    int l0 = blockIdx.x * 32;
    int b  = blockIdx.y;
    for (int idx = tid; idx < 36 * 64; idx += 256) {
        int r = idx >> 6, ci = idx & 63;
        int l = l0 - 2 + r;
        float v = (l >= 0 && l < SEQL) ? in[((size_t)b * SEQL + l) * INDIM + ci] : 0.f;
        ins2[idx] = pk2(v, v);
    }
    __syncthreads();

    int tu = tid & 127;
    int lh = tid >> 7;
    int lbase = lh * 16;
    ull acc[16];
    ull binit = *(const ull*)&cb[2 * tu];
    #pragma unroll
    for (int j = 0; j < 16; j++) acc[j] = binit;

    for (int i = 0; i < 64; i++) {
        ull v2[20];
        #pragma unroll
        for (int r = 0; r < 20; r++) v2[r] = ins2[(lbase + r) * 64 + i];
        #pragma unroll
        for (int w = 0; w < 5; w++) {
            ull kw2 = *(const ull*)&ck[((size_t)(w * 64 + i)) * 256 + 2 * tu];
            #pragma unroll
            for (int j = 0; j < 16; j++) ffma2(acc[j], v2[j + w], kw2);
        }
    }
    #pragma unroll
    for (int j = 0; j < 16; j++) {
        float a, c2; upk2(acc[j], a, c2);
        float2 o = make_float2(fmaxf(a, 0.f), fmaxf(c2, 0.f));
        *(float2*)&d_X[((size_t)b * SEQL + l0 + lbase + j) * UNITS + 2 * tu] = o;
    }
}

// ---------------- ZX = X @ enc_W + enc_b (M=131072, N=1024, K=256), f32x2 ----------------
__global__ __launch_bounds__(256) void gemm_zx_kernel(
    const float* __restrict__ W, const float* __restrict__ bias)
{
    __shared__ __align__(16) ull   As2[8 * 128];
    __shared__ __align__(16) float Bs [8 * 128];
    int tid = threadIdx.x;
    int n0 = blockIdx.x * 128;
    int m0 = blockIdx.y * 128;
    ull acc[8][4];
    #pragma unroll
    for (int i = 0; i < 8; i++)
        #pragma unroll
        for (int j = 0; j < 4; j++) acc[i][j] = 0ull;

    int tx = tid & 15, ty = tid >> 4;
    int am = tid >> 1, ak = (tid & 1) * 4;
    int bk = tid >> 5, bn = (tid & 31) * 4;

    for (int k0 = 0; k0 < 256; k0 += 8) {
        float4 av = *(const float4*)&d_X[(size_t)(m0 + am) * 256 + k0 + ak];
        float4 bv = *(const float4*)&W[(size_t)(k0 + bk) * G4 + n0 + bn];
        As2[(ak + 0) * 128 + am] = pk2(av.x, av.x);
        As2[(ak + 1) * 128 + am] = pk2(av.y, av.y);
        As2[(ak + 2) * 128 + am] = pk2(av.z, av.z);
        As2[(ak + 3) * 128 + am] = pk2(av.w, av.w);
        *(float4*)&Bs[bk * 128 + bn] = bv;
        __syncthreads();
        #pragma unroll
        for (int k = 0; k < 8; k++) {
            ulonglong2 a01 = *(const ulonglong2*)&As2[k * 128 + ty * 8];
            ulonglong2 a23 = *(const ulonglong2*)&As2[k * 128 + ty * 8 + 2];
            ulonglong2 a45 = *(const ulonglong2*)&As2[k * 128 + ty * 8 + 4];
            ulonglong2 a67 = *(const ulonglong2*)&As2[k * 128 + ty * 8 + 6];
            ulonglong2 bq0 = *(const ulonglong2*)&Bs[k * 128 + tx * 8];
            ulonglong2 bq1 = *(const ulonglong2*)&Bs[k * 128 + tx * 8 + 4];
            ull ad[8] = {a01.x, a01.y, a23.x, a23.y, a45.x, a45.y, a67.x, a67.y};
            ull bp[4] = {bq0.x, bq0.y, bq1.x, bq1.y};
            #pragma unroll
            for (int i = 0; i < 8; i++)
                #pragma unroll
                for (int j = 0; j < 4; j++) ffma2(acc[i][j], ad[i], bp[j]);
        }
        __syncthreads();
    }
    #pragma unroll
    for (int i = 0; i < 8; i++) {
        int m = m0 + ty * 8 + i;
        int bIdx = m >> 9;
        int t    = m & 511;
        float* crow = d_ZX + ((size_t)t * BATCH + bIdx) * G4 + n0 + tx * 8;
        const float* brow = bias + n0 + tx * 8;
        #pragma unroll
        for (int j = 0; j < 4; j++) {
            float lo, hi; upk2(acc[i][j], lo, hi);
            crow[j * 2 + 0] = lo + brow[j * 2 + 0];
            crow[j * 2 + 1] = hi + brow[j * 2 + 1];
        }
    }
}

// no-op pad so lstm_persistent is launch index 3 (ncu capture slot)
__global__ void pad_kernel() {}

// ---------------- grid barrier ----------------
__device__ __forceinline__ void grid_sync() {
    __threadfence();
    __syncthreads();
    if (threadIdx.x == 0) {
        unsigned gen = *(volatile unsigned*)&g_gen;
        if (atomicAdd(&g_cnt, 1u) == NCTA_REC - 1) {
            *(volatile unsigned*)&g_cnt = 0;
            __threadfence();
            atomicAdd(&g_gen, 1u);
        } else {
            while (*(volatile unsigned*)&g_gen == gen) { }
        }
        __threadfence();
    }
    __syncthreads();
}

// ---------------- persistent LSTM: single-pass step ----------------
// 128 CTAs x 256 threads. CTA = 16 units (64 gate-cols) x 32 batches, K=256.
// Compute role: (kq = tid>>5 k-slice of 32, cp = tid&31 col pair).
//   Ureg[32] dup pairs in registers, h dup pairs in smem (broadcast LDS),
//   acc over all 32 batches. One split-k reduction, one gate phase per step.
// Gate role: (guu = tid&15 unit, gbl = tid>>4) handles batches gbl and gbl+16.
__global__ __launch_bounds__(256, 1) void lstm_persistent(
    const float* __restrict__ encU, const float* __restrict__ cellW,
    const float* __restrict__ cellU, const float* __restrict__ cellB)
{
    extern __shared__ char smem_raw[];
    ull* hdup = (ull*)smem_raw;                 // [32 b][256 k] dup pairs, 64 KB
    ull* red  = (ull*)(smem_raw + 65536);       // [32 b][8 kq][32 cp],     64 KB

    int tid = threadIdx.x;
    int kq = tid >> 5;          // 0..7
    int cp = tid & 31;          // 0..31
    int ct = blockIdx.x & 15;
    int bt = blockIdx.x >> 4;
    int u0 = ct * 16;
    int b0 = bt * 32;
    int uu_c = cp >> 1;
    int gb   = (cp & 1) * 2;    // 0 -> (i,f) lanes, 2 -> (g,o) lanes

    int guu = tid & 15;
    int gbl = tid >> 4;         // 0..15
    int gu  = u0 + guu;

    // ---- encoder U into registers (once) ----
    ull Ureg[32];
    {
        const float* up = encU + (size_t)(kq * 32) * G4 + gb * 256 + u0 + uu_c;
        #pragma unroll
        for (int k = 0; k < 32; k++)
            Ureg[k] = pk2(__ldg(up + (size_t)k * G4), __ldg(up + (size_t)k * G4 + 256));
    }

    float cst[2] = {0.f, 0.f};
    float bz[4]  = {0.f, 0.f, 0.f, 0.f};

    #pragma unroll 1
    for (int s = 0; s < SEQL + OUTSTEPS; s++) {
        int dec = (s >= SEQL);
        int t = dec ? s - SEQL : s;

        if (s == SEQL) {   // decoder weights: cell_W + cell_U folded
            const float* wp = cellW + (size_t)(kq * 32) * G4 + gb * 256 + u0 + uu_c;
            const float* vp = cellU + (size_t)(kq * 32) * G4 + gb * 256 + u0 + uu_c;
            #pragma unroll
            for (int k = 0; k < 32; k++) {
                size_t o = (size_t)k * G4;
                Ureg[k] = pk2(__ldg(wp + o) + __ldg(vp + o),
                              __ldg(wp + o + 256) + __ldg(vp + o + 256));
            }
            #pragma unroll
            for (int g = 0; g < 4; g++) bz[g] = __ldg(cellB + g * 256 + gu);
        }

        // ---- stage h_prev as dup pairs, b-major ----
        if (s == 0) {
            for (int idx = tid; idx < 32 * 256; idx += 256) hdup[idx] = 0ull;
        } else {
            const float* hin = d_Hbuf[s & 1];
            #pragma unroll
            for (int i = 0; i < 8; i++) {
                int flat = tid + 256 * i;
                int k4 = (flat & 63) * 4;
                int bl = flat >> 6;
                float4 v = __ldcg((const float4*)(hin + (size_t)(b0 + bl) * UNITS + k4));
                ull* dst = hdup + bl * 256 + k4;
                dst[0] = pk2(v.x, v.x); dst[1] = pk2(v.y, v.y);
                dst[2] = pk2(v.z, v.z); dst[3] = pk2(v.w, v.w);
            }
        }

        // ---- z-init (gate role): 2 batches ----
        float zini[2][4];
        if (!dec) {
            #pragma unroll
            for (int p = 0; p < 2; p++) {
                int b = b0 + p * 16 + gbl;
                const float* r = d_ZX + ((size_t)t * BATCH + b) * G4 + gu;
                #pragma unroll
                for (int g = 0; g < 4; g++) zini[p][g] = __ldcg(r + g * 256);
            }
        } else {
            #pragma unroll
            for (int p = 0; p < 2; p++)
                #pragma unroll
                for (int g = 0; g < 4; g++) zini[p][g] = bz[g];
        }
        __syncthreads();

        // ---- partial z = h @ U over k-slice, all 32 batches ----
        ull acc[32];
        #pragma unroll
        for (int b = 0; b < 32; b++) acc[b] = 0ull;

        #pragma unroll 4
        for (int kk = 0; kk < 16; kk++) {
            #pragma unroll
            for (int b = 0; b < 32; b++) {
                ulonglong2 h2 = *(const ulonglong2*)
                    &hdup[b * 256 + kq * 32 + kk * 2];
                ffma2(acc[b], h2.x, Ureg[kk * 2]);
                ffma2(acc[b], h2.y, Ureg[kk * 2 + 1]);
            }
        }

        // ---- split-k reduction ----
        #pragma unroll
        for (int b = 0; b < 32; b++)
            red[(b * 8 + kq) * 32 + cp] = acc[b];
        __syncthreads();

        // ---- gates (thread = (guu, gbl)), batches gbl and gbl+16 ----
        float* hout = d_Hbuf[(s + 1) & 1];
        #pragma unroll
        for (int p = 0; p < 2; p++) {
            int bl = p * 16 + gbl;
            ull zif = 0ull, zgo = 0ull;
            #pragma unroll
            for (int q = 0; q < 8; q++) {
                ulonglong2 v = *(const ulonglong2*)&red[(bl * 8 + q) * 32 + 2 * guu];
                fadd2(zif, v.x);
                fadd2(zgo, v.y);
            }
            float zi, zf, zg, zo;
            upk2(zif, zi, zf);
            upk2(zgo, zg, zo);
            zi += zini[p][0]; zf += zini[p][1]; zg += zini[p][2]; zo += zini[p][3];

            float ig = fast_sigmoid(zi);
            float fg = fast_sigmoid(zf);
            float gg = fast_tanh(zg);
            float og = fast_sigmoid(zo);
            float cn = fg * cst[p] + ig * gg;
            float hn = og * fast_tanh(cn);
            cst[p] = cn;

            int b = b0 + bl;
            hout[(size_t)b * UNITS + gu] = hn;
            if (!dec) d_HSEQ[((size_t)b * SEQL + t) * UNITS + gu] = hn;
            else      d_FSEQ[((size_t)b * OUTSTEPS + t) * UNITS + gu] = hn;
        }

        grid_sync();
    }
}

// ---------------- backcast = HSEQ @ back_W + back_b (M=131072, N=64, K=256), f32x2 ----------------
__global__ __launch_bounds__(256) void gemm_back_kernel(
    const float* __restrict__ Bw, const float* __restrict__ bias, float* __restrict__ out)
{
    __shared__ __align__(16) ull   As2[16 * 64];
    __shared__ __align__(16) float Bs [16 * 64];
    int tid = threadIdx.x;
    int m0 = blockIdx.x * 64;
    int tx = tid & 15, ty = tid >> 4;
    ull acc[4][2];
    #pragma unroll
    for (int i = 0; i < 4; i++) { acc[i][0] = 0ull; acc[i][1] = 0ull; }
    int lam = tid >> 2, lak = (tid & 3) * 4;
    int lbk = tid >> 4, lbn = (tid & 15) * 4;
    for (int k0 = 0; k0 < 256; k0 += 16) {
        float4 av = *(const float4*)&d_HSEQ[(size_t)(m0 + lam) * 256 + k0 + lak];
        float4 bv = *(const float4*)&Bw[(size_t)(k0 + lbk) * 64 + lbn];
        As2[(lak + 0) * 64 + lam] = pk2(av.x, av.x);
        As2[(lak + 1) * 64 + lam] = pk2(av.y, av.y);
        As2[(lak + 2) * 64 + lam] = pk2(av.z, av.z);
        As2[(lak + 3) * 64 + lam] = pk2(av.w, av.w);
        *(float4*)&Bs[lbk * 64 + lbn] = bv;
        __syncthreads();
        #pragma unroll
        for (int k = 0; k < 16; k++) {
            ulonglong2 a01 = *(const ulonglong2*)&As2[k * 64 + ty * 4];
            ulonglong2 a23 = *(const ulonglong2*)&As2[k * 64 + ty * 4 + 2];
            ulonglong2 bq  = *(const ulonglong2*)&Bs[k * 64 + tx * 4];
            ffma2(acc[0][0], a01.x, bq.x); ffma2(acc[0][1], a01.x, bq.y);
            ffma2(acc[1][0], a01.y, bq.x); ffma2(acc[1][1], a01.y, bq.y);
            ffma2(acc[2][0], a23.x, bq.x); ffma2(acc[2][1], a23.x, bq.y);
            ffma2(acc[3][0], a23.y, bq.x); ffma2(acc[3][1], a23.y, bq.y);
        }
        __syncthreads();
    }
    #pragma unroll
    for (int i = 0; i < 4; i++) {
        int m = m0 + ty * 4 + i;
        #pragma unroll
        for (int j = 0; j < 2; j++) {
            float lo, hi; upk2(acc[i][j], lo, hi);
            int n = tx * 4 + j * 2;
            out[(size_t)m * 64 + n]     = lo + bias[n];
            out[(size_t)m * 64 + n + 1] = hi + bias[n + 1];
        }
    }
}

// ---------------- forecast = FSEQ @ fore_W + fore_b ----------------
__global__ __launch_bounds__(256) void forecast_kernel(
    const float* __restrict__ Wf, const float* __restrict__ bf, float* __restrict__ out)
{
    __shared__ __align__(16) float rows[8][256];
    int tid = threadIdx.x;
    int m0 = blockIdx.x * 8;
    #pragma unroll
    for (int i = 0; i < 8; i++) {
        int flat = tid + 256 * i;
        int r = flat >> 8, cc = flat & 255;
        rows[r][cc] = d_FSEQ[(size_t)(m0 + r) * 256 + cc];
    }
    __syncthreads();
    int r = tid >> 5, n = tid & 31;
    float acc = bf[n];
    #pragma unroll 8
    for (int k = 0; k < 256; k++) acc += rows[r][k] * Wf[k * 32 + n];
    out[(size_t)(m0 + r) * 32 + n] = acc;
}

// ---------------- launch ----------------
extern "C" void kernel_launch(void* const* d_in, const int* in_sizes, int n_in,
                              void* d_out, int out_size)
{
    const float* inputs = (const float*)d_in[0];
    const float* conv_k = (const float*)d_in[1];
    const float* conv_b = (const float*)d_in[2];
    const float* enc_W  = (const float*)d_in[3];
    const float* enc_U  = (const float*)d_in[4];
    const float* enc_b  = (const float*)d_in[5];
    const float* cell_W = (const float*)d_in[6];
    const float* cell_U = (const float*)d_in[7];
    const float* cell_b = (const float*)d_in[8];
    const float* fore_W = (const float*)d_in[9];
    const float* fore_b = (const float*)d_in[10];
    const float* back_W = (const float*)d_in[11];
    const float* back_b = (const float*)d_in[12];
    float* out = (float*)d_out;

    const int rec_smem = 65536 + 65536;   // hdup + red = 128 KB
    cudaFuncSetAttribute(lstm_persistent,
                         cudaFuncAttributeMaxDynamicSharedMemorySize, rec_smem);

    conv_relu_kernel<<<dim3(SEQL / 32, BATCH), 256>>>(inputs, conv_k, conv_b);   // idx 0
    gemm_zx_kernel<<<dim3(G4 / 128, (BATCH * SEQL) / 128), 256>>>(enc_W, enc_b); // idx 1
    pad_kernel<<<1, 32>>>();                                                     // idx 2
    lstm_persistent<<<NCTA_REC, 256, rec_smem>>>(enc_U, cell_W, cell_U, cell_b); // idx 3 (ncu slot)
    forecast_kernel<<<(BATCH * OUTSTEPS) / 8, 256>>>(fore_W, fore_b, out);
    gemm_back_kernel<<<(BATCH * SEQL) / 64, 256>>>(back_W, back_b,
                                                   out + (size_t)BATCH * OUTSTEPS * OUTDIMS);
}

// round 5
// speedup vs baseline: 1.5781x; 1.5781x over previous
#include <cuda_runtime.h>
#include <cstdint>
#include <math.h>

#define BATCH    256
#define SEQL     512
#define INDIM    64
#define UNITS    256
#define OUTSTEPS 64
#define OUTDIMS  32
#define G4       1024   // 4 * UNITS
#define NCTA_REC 128

typedef unsigned long long ull;

// ---------------- scratch (static device globals; no allocation) ----------------
__device__ float d_X[BATCH * SEQL * UNITS];            // conv output
__device__ float d_ZX[(size_t)SEQL * BATCH * G4];      // x@W + b, [t][b][1024]
__device__ float d_HSEQ[BATCH * SEQL * UNITS];         // encoder hidden seq (also h exchange)
__device__ float d_FSEQ[BATCH * OUTSTEPS * UNITS];     // decoder hidden seq (also h exchange)
__device__ unsigned g_cnt = 0;                          // grid barrier
__device__ unsigned g_gen = 0;

// ---------------- f32x2 helpers ----------------
__device__ __forceinline__ ull pk2(float lo, float hi) {
    ull r; asm("mov.b64 %0, {%1, %2};" : "=l"(r) : "f"(lo), "f"(hi)); return r;
}
__device__ __forceinline__ void upk2(ull v, float& lo, float& hi) {
    asm("mov.b64 {%0, %1}, %2;" : "=f"(lo), "=f"(hi) : "l"(v));
}
__device__ __forceinline__ void ffma2(ull& d, ull a, ull b) {
    asm("fma.rn.f32x2 %0, %1, %2, %0;" : "+l"(d) : "l"(a), "l"(b));
}
__device__ __forceinline__ void fadd2(ull& d, ull a) {
    asm("add.rn.f32x2 %0, %0, %1;" : "+l"(d) : "l"(a));
}

// fast, overflow-safe gate functions (MUFU-based, ~1e-6 rel err)
__device__ __forceinline__ float fast_sigmoid(float x) {
    return __fdividef(1.f, 1.f + __expf(-x));
}
__device__ __forceinline__ float fast_tanh(float x) {
    float e = __expf(-2.f * fabsf(x));
    float t = __fdividef(1.f - e, 1.f + e);
    return copysignf(t, x);
}

// ---------------- conv1d 'same' (K=5) + bias + relu, f32x2 over unit pairs ----------------
__global__ __launch_bounds__(256) void conv_relu_kernel(
    const float* __restrict__ in, const float* __restrict__ ck, const float* __restrict__ cb)
{
    __shared__ __align__(16) ull ins2[36 * 64];
    int tid = threadIdx.x;
    int l0 = blockIdx.x * 32;
    int b  = blockIdx.y;
    for (int idx = tid; idx < 36 * 64; idx += 256) {
        int r = idx >> 6, ci = idx & 63;
        int l = l0 - 2 + r;
        float v = (l >= 0 && l < SEQL) ? in[((size_t)b * SEQL + l) * INDIM + ci] : 0.f;
        ins2[idx] = pk2(v, v);
    }
    __syncthreads();

    int tu = tid & 127;
    int lh = tid >> 7;
    int lbase = lh * 16;
    ull acc[16];
    ull binit = *(const ull*)&cb[2 * tu];
    #pragma unroll
    for (int j = 0; j < 16; j++) acc[j] = binit;

    for (int i = 0; i < 64; i++) {
        ull v2[20];
        #pragma unroll
        for (int r = 0; r < 20; r++) v2[r] = ins2[(lbase + r) * 64 + i];
        #pragma unroll
        for (int w = 0; w < 5; w++) {
            ull kw2 = *(const ull*)&ck[((size_t)(w * 64 + i)) * 256 + 2 * tu];
            #pragma unroll
            for (int j = 0; j < 16; j++) ffma2(acc[j], v2[j + w], kw2);
        }
    }
    #pragma unroll
    for (int j = 0; j < 16; j++) {
        float a, c2; upk2(acc[j], a, c2);
        float2 o = make_float2(fmaxf(a, 0.f), fmaxf(c2, 0.f));
        *(float2*)&d_X[((size_t)b * SEQL + l0 + lbase + j) * UNITS + 2 * tu] = o;
    }
}

// ---------------- ZX = X @ enc_W + enc_b (M=131072, N=1024, K=256), f32x2 ----------------
__global__ __launch_bounds__(256) void gemm_zx_kernel(
    const float* __restrict__ W, const float* __restrict__ bias)
{
    __shared__ __align__(16) ull   As2[8 * 128];
    __shared__ __align__(16) float Bs [8 * 128];
    int tid = threadIdx.x;
    int n0 = blockIdx.x * 128;
    int m0 = blockIdx.y * 128;
    ull acc[8][4];
    #pragma unroll
    for (int i = 0; i < 8; i++)
        #pragma unroll
        for (int j = 0; j < 4; j++) acc[i][j] = 0ull;

    int tx = tid & 15, ty = tid >> 4;
    int am = tid >> 1, ak = (tid & 1) * 4;
    int bk = tid >> 5, bn = (tid & 31) * 4;

    for (int k0 = 0; k0 < 256; k0 += 8) {
        float4 av = *(const float4*)&d_X[(size_t)(m0 + am) * 256 + k0 + ak];
        float4 bv = *(const float4*)&W[(size_t)(k0 + bk) * G4 + n0 + bn];
        As2[(ak + 0) * 128 + am] = pk2(av.x, av.x);
        As2[(ak + 1) * 128 + am] = pk2(av.y, av.y);
        As2[(ak + 2) * 128 + am] = pk2(av.z, av.z);
        As2[(ak + 3) * 128 + am] = pk2(av.w, av.w);
        *(float4*)&Bs[bk * 128 + bn] = bv;
        __syncthreads();
        #pragma unroll
        for (int k = 0; k < 8; k++) {
            ulonglong2 a01 = *(const ulonglong2*)&As2[k * 128 + ty * 8];
            ulonglong2 a23 = *(const ulonglong2*)&As2[k * 128 + ty * 8 + 2];
            ulonglong2 a45 = *(const ulonglong2*)&As2[k * 128 + ty * 8 + 4];
            ulonglong2 a67 = *(const ulonglong2*)&As2[k * 128 + ty * 8 + 6];
            ulonglong2 bq0 = *(const ulonglong2*)&Bs[k * 128 + tx * 8];
            ulonglong2 bq1 = *(const ulonglong2*)&Bs[k * 128 + tx * 8 + 4];
            ull ad[8] = {a01.x, a01.y, a23.x, a23.y, a45.x, a45.y, a67.x, a67.y};
            ull bp[4] = {bq0.x, bq0.y, bq1.x, bq1.y};
            #pragma unroll
            for (int i = 0; i < 8; i++)
                #pragma unroll
                for (int j = 0; j < 4; j++) ffma2(acc[i][j], ad[i], bp[j]);
        }
        __syncthreads();
    }
    #pragma unroll
    for (int i = 0; i < 8; i++) {
        int m = m0 + ty * 8 + i;
        int bIdx = m >> 9;
        int t    = m & 511;
        float* crow = d_ZX + ((size_t)t * BATCH + bIdx) * G4 + n0 + tx * 8;
        const float* brow = bias + n0 + tx * 8;
        #pragma unroll
        for (int j = 0; j < 4; j++) {
            float lo, hi; upk2(acc[i][j], lo, hi);
            crow[j * 2 + 0] = lo + brow[j * 2 + 0];
            crow[j * 2 + 1] = hi + brow[j * 2 + 1];
        }
    }
}

// no-op pad so lstm_persistent stays at launch index 3 (ncu capture slot)
__global__ void pad_kernel() {}

// ---------------- cheap grid barrier (CG-style: fence only in elected thread) ----------------
__device__ __forceinline__ void grid_sync() {
    __syncthreads();                 // CTA writes visible to tid0 (cta scope)
    if (threadIdx.x == 0) {
        unsigned gen = *(volatile unsigned*)&g_gen;
        __threadfence();             // cumulative release: publish CTA's writes gpu-wide
        if (atomicAdd(&g_cnt, 1u) == NCTA_REC - 1) {
            *(volatile unsigned*)&g_cnt = 0;
            __threadfence();
            atomicAdd(&g_gen, 1u);
        } else {
            while (*(volatile unsigned*)&g_gen == gen) { }
        }
        __threadfence();             // acquire: other CTAs' writes now visible
    }
    __syncthreads();
}

// ---------------- persistent LSTM: R3 2-pass structure + cheap barrier + fast gates ----------------
// 128 CTAs x 256 threads. CTA = 16 units (64 gate-cols) x 32 batches, K=256.
// Compute role: (kq = tid>>5 k-slice of 32, cp = tid&31 col pair),
//   Ureg[32] dup pairs in registers, h dup pairs in smem (broadcast LDS),
//   acc[16] per pass (2 passes of 16 batches). Split-k reduced via smem.
// Gate role: (guu = tid&15 unit, gbl = tid>>4 batch). h written only to HSEQ/FSEQ.
__global__ __launch_bounds__(256, 1) void lstm_persistent(
    const float* __restrict__ encU, const float* __restrict__ cellW,
    const float* __restrict__ cellU, const float* __restrict__ cellB)
{
    extern __shared__ char smem_raw[];
    ull* hdup = (ull*)smem_raw;                 // [32 b][256 k] dup pairs, 64 KB
    ull* red  = (ull*)(smem_raw + 65536);       // [16 b][8 kq][32 cp],     32 KB

    int tid = threadIdx.x;
    int kq = tid >> 5;          // 0..7
    int cp = tid & 31;          // 0..31
    int ct = blockIdx.x & 15;
    int bt = blockIdx.x >> 4;
    int u0 = ct * 16;
    int b0 = bt * 32;
    int uu_c = cp >> 1;
    int gb   = (cp & 1) * 2;    // 0 -> (i,f) lanes, 2 -> (g,o) lanes

    int guu = tid & 15;
    int gbl = tid >> 4;         // 0..15
    int gu  = u0 + guu;

    // ---- encoder U into registers (once) ----
    ull Ureg[32];
    {
        const float* up = encU + (size_t)(kq * 32) * G4 + gb * 256 + u0 + uu_c;
        #pragma unroll
        for (int k = 0; k < 32; k++)
            Ureg[k] = pk2(__ldg(up + (size_t)k * G4), __ldg(up + (size_t)k * G4 + 256));
    }

    float cst[2] = {0.f, 0.f};
    float bz[4]  = {0.f, 0.f, 0.f, 0.f};

    #pragma unroll 1
    for (int s = 0; s < SEQL + OUTSTEPS; s++) {
        int dec = (s >= SEQL);
        int t = dec ? s - SEQL : s;

        if (s == SEQL) {   // decoder weights: cell_W + cell_U folded
            const float* wp = cellW + (size_t)(kq * 32) * G4 + gb * 256 + u0 + uu_c;
            const float* vp = cellU + (size_t)(kq * 32) * G4 + gb * 256 + u0 + uu_c;
            #pragma unroll
            for (int k = 0; k < 32; k++) {
                size_t o = (size_t)k * G4;
                Ureg[k] = pk2(__ldg(wp + o) + __ldg(vp + o),
                              __ldg(wp + o + 256) + __ldg(vp + o + 256));
            }
            #pragma unroll
            for (int g = 0; g < 4; g++) bz[g] = __ldg(cellB + g * 256 + gu);
        }

        // ---- stage h_prev (from HSEQ/FSEQ) as dup pairs, b-major ----
        if (s == 0) {
            for (int idx = tid; idx < 32 * 256; idx += 256) hdup[idx] = 0ull;
        } else {
            #pragma unroll
            for (int i = 0; i < 8; i++) {
                int flat = tid + 256 * i;
                int k4 = (flat & 63) * 4;
                int bl = flat >> 6;
                int b = b0 + bl;
                const float4* src;
                if (s <= SEQL)
                    src = (const float4*)(d_HSEQ + ((size_t)b * SEQL + (s - 1)) * UNITS + k4);
                else
                    src = (const float4*)(d_FSEQ + ((size_t)b * OUTSTEPS + (s - 1 - SEQL)) * UNITS + k4);
                float4 v = __ldcg(src);
                ull* dst = hdup + bl * 256 + k4;
                dst[0] = pk2(v.x, v.x); dst[1] = pk2(v.y, v.y);
                dst[2] = pk2(v.z, v.z); dst[3] = pk2(v.w, v.w);
            }
        }

        // ---- z-init (gate role) ----
        float zini[2][4];
        if (!dec) {
            #pragma unroll
            for (int p = 0; p < 2; p++) {
                int b = b0 + p * 16 + gbl;
                const float* r = d_ZX + ((size_t)t * BATCH + b) * G4 + gu;
                #pragma unroll
                for (int g = 0; g < 4; g++) zini[p][g] = __ldcg(r + g * 256);
            }
        } else {
            #pragma unroll
            for (int p = 0; p < 2; p++)
                #pragma unroll
                for (int g = 0; g < 4; g++) zini[p][g] = bz[g];
        }
        __syncthreads();

        #pragma unroll 1
        for (int p = 0; p < 2; p++) {
            int boff = p * 16;

            // ---- partial z = h @ U over this thread's k-slice (16 batches) ----
            ull acc[16];
            #pragma unroll
            for (int b = 0; b < 16; b++) acc[b] = 0ull;

            #pragma unroll
            for (int kk = 0; kk < 16; kk++) {
                #pragma unroll
                for (int b = 0; b < 16; b++) {
                    ulonglong2 h2 = *(const ulonglong2*)
                        &hdup[(boff + b) * 256 + kq * 32 + kk * 2];
                    ffma2(acc[b], h2.x, Ureg[kk * 2]);
                    ffma2(acc[b], h2.y, Ureg[kk * 2 + 1]);
                }
            }

            // ---- split-k reduction via smem ----
            #pragma unroll
            for (int b = 0; b < 16; b++)
                red[(b * 8 + kq) * 32 + cp] = acc[b];
            __syncthreads();

            // ---- gates (thread = (guu, gbl)) ----
            ull zif = 0ull, zgo = 0ull;
            #pragma unroll
            for (int q = 0; q < 8; q++) {
                ulonglong2 v = *(const ulonglong2*)&red[(gbl * 8 + q) * 32 + 2 * guu];
                fadd2(zif, v.x);
                fadd2(zgo, v.y);
            }
            float zi, zf, zg, zo;
            upk2(zif, zi, zf);
            upk2(zgo, zg, zo);
            zi += zini[p][0]; zf += zini[p][1]; zg += zini[p][2]; zo += zini[p][3];

            float ig = fast_sigmoid(zi);
            float fg = fast_sigmoid(zf);
            float gg = fast_tanh(zg);
            float og = fast_sigmoid(zo);
            float cn = fg * cst[p] + ig * gg;
            float hn = og * fast_tanh(cn);
            cst[p] = cn;

            int b = b0 + boff + gbl;
            if (!dec) d_HSEQ[((size_t)b * SEQL + t) * UNITS + gu] = hn;
            else      d_FSEQ[((size_t)b * OUTSTEPS + t) * UNITS + gu] = hn;

            __syncthreads();   // red reused by next pass
        }

        grid_sync();
    }
}

// ---------------- backcast = HSEQ @ back_W + back_b (M=131072, N=64, K=256), f32x2 ----------------
__global__ __launch_bounds__(256) void gemm_back_kernel(
    const float* __restrict__ Bw, const float* __restrict__ bias, float* __restrict__ out)
{
    __shared__ __align__(16) ull   As2[16 * 64];
    __shared__ __align__(16) float Bs [16 * 64];
    int tid = threadIdx.x;
    int m0 = blockIdx.x * 64;
    int tx = tid & 15, ty = tid >> 4;
    ull acc[4][2];
    #pragma unroll
    for (int i = 0; i < 4; i++) { acc[i][0] = 0ull; acc[i][1] = 0ull; }
    int lam = tid >> 2, lak = (tid & 3) * 4;
    int lbk = tid >> 4, lbn = (tid & 15) * 4;
    for (int k0 = 0; k0 < 256; k0 += 16) {
        float4 av = *(const float4*)&d_HSEQ[(size_t)(m0 + lam) * 256 + k0 + lak];
        float4 bv = *(const float4*)&Bw[(size_t)(k0 + lbk) * 64 + lbn];
        As2[(lak + 0) * 64 + lam] = pk2(av.x, av.x);
        As2[(lak + 1) * 64 + lam] = pk2(av.y, av.y);
        As2[(lak + 2) * 64 + lam] = pk2(av.z, av.z);
        As2[(lak + 3) * 64 + lam] = pk2(av.w, av.w);
        *(float4*)&Bs[lbk * 64 + lbn] = bv;
        __syncthreads();
        #pragma unroll
        for (int k = 0; k < 16; k++) {
            ulonglong2 a01 = *(const ulonglong2*)&As2[k * 64 + ty * 4];
            ulonglong2 a23 = *(const ulonglong2*)&As2[k * 64 + ty * 4 + 2];
            ulonglong2 bq  = *(const ulonglong2*)&Bs[k * 64 + tx * 4];
            ffma2(acc[0][0], a01.x, bq.x); ffma2(acc[0][1], a01.x, bq.y);
            ffma2(acc[1][0], a01.y, bq.x); ffma2(acc[1][1], a01.y, bq.y);
            ffma2(acc[2][0], a23.x, bq.x); ffma2(acc[2][1], a23.x, bq.y);
            ffma2(acc[3][0], a23.y, bq.x); ffma2(acc[3][1], a23.y, bq.y);
        }
        __syncthreads();
    }
    #pragma unroll
    for (int i = 0; i < 4; i++) {
        int m = m0 + ty * 4 + i;
        #pragma unroll
        for (int j = 0; j < 2; j++) {
            float lo, hi; upk2(acc[i][j], lo, hi);
            int n = tx * 4 + j * 2;
            out[(size_t)m * 64 + n]     = lo + bias[n];
            out[(size_t)m * 64 + n + 1] = hi + bias[n + 1];
        }
    }
}

// ---------------- forecast = FSEQ @ fore_W + fore_b ----------------
__global__ __launch_bounds__(256) void forecast_kernel(
    const float* __restrict__ Wf, const float* __restrict__ bf, float* __restrict__ out)
{
    __shared__ __align__(16) float rows[8][256];
    int tid = threadIdx.x;
    int m0 = blockIdx.x * 8;
    #pragma unroll
    for (int i = 0; i < 8; i++) {
        int flat = tid + 256 * i;
        int r = flat >> 8, cc = flat & 255;
        rows[r][cc] = d_FSEQ[(size_t)(m0 + r) * 256 + cc];
    }
    __syncthreads();
    int r = tid >> 5, n = tid & 31;
    float acc = bf[n];
    #pragma unroll 8
    for (int k = 0; k < 256; k++) acc += rows[r][k] * Wf[k * 32 + n];
    out[(size_t)(m0 + r) * 32 + n] = acc;
}

// ---------------- launch ----------------
extern "C" void kernel_launch(void* const* d_in, const int* in_sizes, int n_in,
                              void* d_out, int out_size)
{
    const float* inputs = (const float*)d_in[0];
    const float* conv_k = (const float*)d_in[1];
    const float* conv_b = (const float*)d_in[2];
    const float* enc_W  = (const float*)d_in[3];
    const float* enc_U  = (const float*)d_in[4];
    const float* enc_b  = (const float*)d_in[5];
    const float* cell_W = (const float*)d_in[6];
    const float* cell_U = (const float*)d_in[7];
    const float* cell_b = (const float*)d_in[8];
    const float* fore_W = (const float*)d_in[9];
    const float* fore_b = (const float*)d_in[10];
    const float* back_W = (const float*)d_in[11];
    const float* back_b = (const float*)d_in[12];
    float* out = (float*)d_out;

    const int rec_smem = 65536 + 32768;   // hdup + red = 96 KB
    cudaFuncSetAttribute(lstm_persistent,
                         cudaFuncAttributeMaxDynamicSharedMemorySize, rec_smem);

    conv_relu_kernel<<<dim3(SEQL / 32, BATCH), 256>>>(inputs, conv_k, conv_b);   // idx 0
    gemm_zx_kernel<<<dim3(G4 / 128, (BATCH * SEQL) / 128), 256>>>(enc_W, enc_b); // idx 1
    pad_kernel<<<1, 32>>>();                                                     // idx 2
    lstm_persistent<<<NCTA_REC, 256, rec_smem>>>(enc_U, cell_W, cell_U, cell_b); // idx 3 (ncu slot)
    forecast_kernel<<<(BATCH * OUTSTEPS) / 8, 256>>>(fore_W, fore_b, out);
    gemm_back_kernel<<<(BATCH * SEQL) / 64, 256>>>(back_W, back_b,
                                                   out + (size_t)BATCH * OUTSTEPS * OUTDIMS);
}